// round 6
// baseline (speedup 1.0000x reference)
#include <cuda_runtime.h>
#include <cuda_bf16.h>
#include <math.h>

// Problem dims (fixed by the dataset)
#define BB 8
#define HH 8
#define LL 4096
#define KN 16
#define DD 256
#define DHH 64
#define NROWS (BB*LL)          // 32768

// Scratch (no allocation allowed -> __device__ globals)
__device__ float g_std[NROWS];
__device__ float g_mods[NROWS*3];
__device__ float g_mn[BB];
__device__ float g_mx[BB];

__device__ __forceinline__ float warp_sum(float v) {
    #pragma unroll
    for (int o = 16; o > 0; o >>= 1) v += __shfl_xor_sync(0xffffffffu, v, o);
    return v;
}

__device__ __forceinline__ float gelu_exact(float x) {
    return 0.5f * x * (1.f + erff(x * 0.70710678118654752f));
}

// ---------------------------------------------------------------------------
// K1: per-row feature_std (ddof=1) + MLP mods (gelu -> LN -> 3 outputs).
// 32 rows per block, 128 threads. 4x4 register tile for the 256x64 matvec so
// w1 is loaded once per 32 rows (through L1), FFMA-bound instead of L2-bound.
// ---------------------------------------------------------------------------
__global__ void __launch_bounds__(128)
k1_std_mlp(const float* __restrict__ latents,
           const float* __restrict__ w1,   // (256,64)
           const float* __restrict__ b1,   // (64,)
           const float* __restrict__ lng,  // (64,)
           const float* __restrict__ lnb,  // (64,)
           const float* __restrict__ w2,   // (64,3)
           const float* __restrict__ b2)   // (3,)
{
    __shared__ __align__(16) float lat_s[DD * 36];   // transposed, padded: [d][row]
    __shared__ __align__(16) float hmat[32 * 68];    // [row][j] padded

    const int t = threadIdx.x;
    const int row0 = blockIdx.x * 32;

    // load 32 rows of latents, transposed into lat_s[d*36 + r]
    for (int idx = t; idx < 32 * DD; idx += 128) {
        int r = idx >> 8;          // row within tile
        int d = idx & 255;
        lat_s[d * 36 + r] = latents[(size_t)(row0 + r) * DD + d];
    }
    __syncthreads();

    const int w = t >> 5, lane = t & 31;

    // ---- std phase: warp per row (4 warps x 8 rows) ----
    for (int r = w; r < 32; r += 4) {
        float v[8];
        float s = 0.f;
        #pragma unroll
        for (int i = 0; i < 8; i++) { v[i] = lat_s[(lane + i * 32) * 36 + r]; s += v[i]; }
        s = warp_sum(s);
        float mean = s * (1.f / 256.f);
        float sq = 0.f;
        #pragma unroll
        for (int i = 0; i < 8; i++) { float dv = v[i] - mean; sq += dv * dv; }
        sq = warp_sum(sq);
        if (lane == 0) g_std[row0 + r] = sqrtf(sq * (1.f / 255.f));
    }

    // ---- MLP layer 1: thread (rg,jg) computes rows rg*4..+3, cols jg*4..+3 ----
    const int rg = t >> 4;   // 0..7
    const int jg = t & 15;   // 0..15
    float4 acc0 = {0,0,0,0}, acc1 = {0,0,0,0}, acc2 = {0,0,0,0}, acc3 = {0,0,0,0};
    const float4* __restrict__ w1v = (const float4*)w1;   // idx d*16 + jg
    #pragma unroll 4
    for (int d = 0; d < DD; d++) {
        float4 wv = __ldg(&w1v[d * 16 + jg]);
        float4 lv = *(const float4*)&lat_s[d * 36 + rg * 4];
        acc0.x += lv.x * wv.x; acc0.y += lv.x * wv.y; acc0.z += lv.x * wv.z; acc0.w += lv.x * wv.w;
        acc1.x += lv.y * wv.x; acc1.y += lv.y * wv.y; acc1.z += lv.y * wv.z; acc1.w += lv.y * wv.w;
        acc2.x += lv.z * wv.x; acc2.y += lv.z * wv.y; acc2.z += lv.z * wv.z; acc2.w += lv.z * wv.w;
        acc3.x += lv.w * wv.x; acc3.y += lv.w * wv.y; acc3.z += lv.w * wv.z; acc3.w += lv.w * wv.w;
    }
    float4 bv = __ldg(&((const float4*)b1)[jg]);
    {
        int r = rg * 4;
        float* p;
        p = &hmat[(r + 0) * 68 + jg * 4];
        p[0] = gelu_exact(acc0.x + bv.x); p[1] = gelu_exact(acc0.y + bv.y);
        p[2] = gelu_exact(acc0.z + bv.z); p[3] = gelu_exact(acc0.w + bv.w);
        p = &hmat[(r + 1) * 68 + jg * 4];
        p[0] = gelu_exact(acc1.x + bv.x); p[1] = gelu_exact(acc1.y + bv.y);
        p[2] = gelu_exact(acc1.z + bv.z); p[3] = gelu_exact(acc1.w + bv.w);
        p = &hmat[(r + 2) * 68 + jg * 4];
        p[0] = gelu_exact(acc2.x + bv.x); p[1] = gelu_exact(acc2.y + bv.y);
        p[2] = gelu_exact(acc2.z + bv.z); p[3] = gelu_exact(acc2.w + bv.w);
        p = &hmat[(r + 3) * 68 + jg * 4];
        p[0] = gelu_exact(acc3.x + bv.x); p[1] = gelu_exact(acc3.y + bv.y);
        p[2] = gelu_exact(acc3.z + bv.z); p[3] = gelu_exact(acc3.w + bv.w);
    }
    __syncthreads();

    // ---- LayerNorm + layer 2: warp per row ----
    for (int rr = w; rr < 32; rr += 4) {
        float a = hmat[rr * 68 + lane];
        float bq = hmat[rr * 68 + 32 + lane];
        float s  = warp_sum(a + bq);
        float sq = warp_sum(a * a + bq * bq);
        float mean = s * (1.f / 64.f);
        float var  = sq * (1.f / 64.f) - mean * mean;
        float rstd = rsqrtf(var + 1e-5f);
        float n0 = (a  - mean) * rstd * __ldg(&lng[lane])      + __ldg(&lnb[lane]);
        float n1 = (bq - mean) * rstd * __ldg(&lng[lane + 32]) + __ldg(&lnb[lane + 32]);
        float m0 = n0 * __ldg(&w2[lane * 3 + 0]) + n1 * __ldg(&w2[(lane + 32) * 3 + 0]);
        float m1 = n0 * __ldg(&w2[lane * 3 + 1]) + n1 * __ldg(&w2[(lane + 32) * 3 + 1]);
        float m2 = n0 * __ldg(&w2[lane * 3 + 2]) + n1 * __ldg(&w2[(lane + 32) * 3 + 2]);
        m0 = warp_sum(m0); m1 = warp_sum(m1); m2 = warp_sum(m2);
        if (lane == 0) {
            int row = row0 + rr;
            g_mods[row * 3 + 0] = m0 + __ldg(&b2[0]);
            g_mods[row * 3 + 1] = m1 + __ldg(&b2[1]);
            g_mods[row * 3 + 2] = m2 + __ldg(&b2[2]);
        }
    }
}

// ---------------------------------------------------------------------------
// K2: per-batch min/max of feature_std over L=4096.
// ---------------------------------------------------------------------------
__global__ void __launch_bounds__(256)
k2_minmax()
{
    __shared__ float smn[256], smx[256];
    const int b = blockIdx.x, t = threadIdx.x;
    float mn = 1e30f, mx = -1e30f;
    for (int i = t; i < LL; i += 256) {
        float v = g_std[b * LL + i];
        mn = fminf(mn, v); mx = fmaxf(mx, v);
    }
    smn[t] = mn; smx[t] = mx;
    __syncthreads();
    for (int s = 128; s > 0; s >>= 1) {
        if (t < s) { smn[t] = fminf(smn[t], smn[t + s]); smx[t] = fmaxf(smx[t], smx[t + s]); }
        __syncthreads();
    }
    if (t == 0) { g_mn[b] = smn[0]; g_mx[b] = smx[0]; }
}

// ---------------------------------------------------------------------------
// K3: main streaming kernel. One block per (b,l): 16 warps = one warp per
// neighbor for the D=256 dot products (HBM-bound part), warp 0 does the
// geometry / softmax / combine epilogue and writes the 2 output floats.
// ---------------------------------------------------------------------------
__global__ void __launch_bounds__(512)
k3_main(const float* __restrict__ latents,
        const float* __restrict__ attn,     // (B,H,L,17)
        const float* __restrict__ nfeat,    // (B,L,K,D)
        const float* __restrict__ npos,     // (B,L,K,2)
        const float* __restrict__ cpos,     // (B,L,2)
        const float* __restrict__ hw,       // (H,)
        const float* __restrict__ p_temp,
        const float* __restrict__ p_lba,
        const float* __restrict__ p_lbr,
        const float* __restrict__ p_imps,
        float* __restrict__ out)            // (B,L,2)
{
    const int bl = blockIdx.x;
    const int b = bl >> 12;
    const int l = bl & (LL - 1);

    __shared__ __align__(16) float lat[DD];
    __shared__ float sim[KN];

    const int t = threadIdx.x, w = t >> 5, lane = t & 31;

    if (t < 64) ((float4*)lat)[t] = ((const float4*)(latents + (size_t)bl * DD))[t];
    __syncthreads();

    // warp w computes similarity with neighbor w
    const float4* __restrict__ nf = (const float4*)(nfeat + (((size_t)bl) * KN + w) * DD);
    float4 a0 = __ldg(&nf[lane]);
    float4 a1 = __ldg(&nf[lane + 32]);
    float4 l0 = ((const float4*)lat)[lane];
    float4 l1 = ((const float4*)lat)[lane + 32];

    float dot = a0.x*l0.x + a0.y*l0.y + a0.z*l0.z + a0.w*l0.w
              + a1.x*l1.x + a1.y*l1.y + a1.z*l1.z + a1.w*l1.w;
    float nsq = a0.x*a0.x + a0.y*a0.y + a0.z*a0.z + a0.w*a0.w
              + a1.x*a1.x + a1.y*a1.y + a1.z*a1.z + a1.w*a1.w;
    float lsq = l0.x*l0.x + l0.y*l0.y + l0.z*l0.z + l0.w*l0.w
              + l1.x*l1.x + l1.y*l1.y + l1.z*l1.z + l1.w*l1.w;
    dot = warp_sum(dot); nsq = warp_sum(nsq); lsq = warp_sum(lsq);
    if (lane == 0) {
        float lnm = fmaxf(sqrtf(lsq), 1e-8f);
        float nnm = fmaxf(sqrtf(nsq), 1e-8f);
        sim[w] = dot / (lnm * nnm);
    }
    __syncthreads();

    if (w != 0) return;

    // ---- warp-0 epilogue (lanes 0..15 carry neighbor state) ----
    const bool act = lane < KN;
    float s = act ? sim[lane] : 0.f;
    float ssum = warp_sum(s);

    // head softmax (each lane computes locally; 8 values)
    float hiv[HH];
    float hmax = -1e30f;
    #pragma unroll
    for (int h = 0; h < HH; h++) { hiv[h] = __ldg(&hw[h]); hmax = fmaxf(hmax, hiv[h]); }
    float hsum = 0.f;
    #pragma unroll
    for (int h = 0; h < HH; h++) { hiv[h] = expf(hiv[h] - hmax); hsum += hiv[h]; }
    float hinv = 1.f / hsum;

    float wa = 0.f;
    if (act) {
        const float* ap = attn + (((size_t)b * HH) * LL + l) * 17 + 1 + lane;
        #pragma unroll
        for (int h = 0; h < HH; h++)
            wa += hiv[h] * hinv * __ldg(&ap[(size_t)h * LL * 17]);
    }

    float2 np = make_float2(0.f, 0.f);
    if (act) np = ((const float2*)npos)[(size_t)bl * KN + lane];
    float2 cp = ((const float2*)cpos)[bl];
    float dx = np.x - cp.x, dy = np.y - cp.y;
    float dist = sqrtf(dx * dx + dy * dy);

    float temp = fabsf(p_temp[0]) + 1e-8f;
    float rs = act ? (expf(s / temp) / (dist + 0.1f)) : 0.f;

    float inv_de = 1.f / (dist + 1e-8f);
    float wa_sum = warp_sum(wa);
    float rs_sum = warp_sum(rs);
    float wcx = warp_sum(wa * np.x);
    float wcy = warp_sum(wa * np.y);
    float rx  = warp_sum(act ? (rs * (-dx * inv_de)) : 0.f);
    float ry  = warp_sum(act ? (rs * (-dy * inv_de)) : 0.f);

    if (lane == 0) {
        float wan = 1.f / (wa_sum + 1e-8f);
        float rsn = 1.f / (rs_sum + 1e-8f);
        float ax = wcx * wan - cp.x;
        float ay = wcy * wan - cp.y;
        float rpx = rx * rsn;
        float rpy = ry * rsn;

        float uniq = 1.f - ssum * (1.f / (float)KN);
        float stdv = g_std[bl];
        float cmpx = (stdv - g_mn[b]) / (g_mx[b] - g_mn[b] + 1e-8f);
        float importance = 0.5f * cmpx + 0.5f * uniq;
        float imps = 1.f / (1.f + expf(-p_imps[0]));
        float escale = 1.f - imps * importance;

        float m0 = g_mods[bl * 3 + 0];
        float m1 = g_mods[bl * 3 + 1];
        float m2 = g_mods[bl * 3 + 2];
        float w_at = expf(p_lba[0]) * 2.f / (1.f + expf(-m0));
        float w_rp = expf(p_lbr[0]) * 2.f / (1.f + expf(-m1));
        float fsc  = escale / (1.f + expf(-m2));
        float inv  = 1.f / (w_at + w_rp + 1e-8f);

        float cx = (w_at * ax + w_rp * rpx) * inv * fsc;
        float cy = (w_at * ay + w_rp * rpy) * inv * fsc;
        out[(size_t)bl * 2 + 0] = tanhf(cx * 0.2f) * 5.f;
        out[(size_t)bl * 2 + 1] = tanhf(cy * 0.2f) * 5.f;
    }
}

// ---------------------------------------------------------------------------
extern "C" void kernel_launch(void* const* d_in, const int* in_sizes, int n_in,
                              void* d_out, int out_size)
{
    (void)in_sizes; (void)n_in; (void)out_size;
    const float* latents = (const float*)d_in[0];
    const float* attn    = (const float*)d_in[1];
    const float* nfeat   = (const float*)d_in[2];
    const float* npos    = (const float*)d_in[3];
    const float* cpos    = (const float*)d_in[4];
    const float* hw      = (const float*)d_in[5];
    const float* p_temp  = (const float*)d_in[6];
    const float* p_lba   = (const float*)d_in[7];
    const float* p_lbr   = (const float*)d_in[8];
    const float* p_imps  = (const float*)d_in[9];
    const float* w1      = (const float*)d_in[10];
    const float* b1      = (const float*)d_in[11];
    const float* lng     = (const float*)d_in[12];
    const float* lnb     = (const float*)d_in[13];
    const float* w2      = (const float*)d_in[14];
    const float* b2      = (const float*)d_in[15];
    float* out = (float*)d_out;

    k1_std_mlp<<<NROWS / 32, 128>>>(latents, w1, b1, lng, lnb, w2, b2);
    k2_minmax<<<BB, 256>>>();
    k3_main<<<NROWS, 512>>>(latents, attn, nfeat, npos, cpos, hw,
                            p_temp, p_lba, p_lbr, p_imps, out);
}

// round 7
// speedup vs baseline: 1.5017x; 1.5017x over previous
#include <cuda_runtime.h>
#include <cuda_bf16.h>
#include <math.h>

#define BB 8
#define HH 8
#define LL 4096
#define KN 16
#define DD 256
#define NROWS (BB*LL)          // 32768

// Scratch (no allocation allowed -> __device__ globals)
__device__ float g_std[NROWS];
__device__ float g_mods[NROWS*3];
__device__ float g_mn[BB];
__device__ float g_mx[BB];

__device__ __forceinline__ float warp_sum(float v) {
    #pragma unroll
    for (int o = 16; o > 0; o >>= 1) v += __shfl_xor_sync(0xffffffffu, v, o);
    return v;
}

__device__ __forceinline__ float gelu_exact(float x) {
    return 0.5f * x * (1.f + erff(x * 0.70710678118654752f));
}

__device__ __forceinline__ float d4(float4 a, float4 b) {
    return a.x*b.x + a.y*b.y + a.z*b.z + a.w*b.w;
}

// ---------------------------------------------------------------------------
// K1: per-row feature_std (ddof=1) + MLP mods (gelu -> LN -> 3 outputs).
// 64 rows/block, 128 threads. Thread tile = 8 rows x 4 cols (32 FFMA per
// 1 LDG.128 + 2 LDS.128). D split into two halves of 128 so the transposed
// latent tile stays under 48KB static smem. LayerNorm + layer 2 done fully
// in registers via half-warp shuffles (no hmat smem).
// ---------------------------------------------------------------------------
__global__ void __launch_bounds__(128)
k1_std_mlp(const float* __restrict__ latents,
           const float* __restrict__ w1,   // (256,64)
           const float* __restrict__ b1,   // (64,)
           const float* __restrict__ lng,  // (64,)
           const float* __restrict__ lnb,  // (64,)
           const float* __restrict__ w2,   // (64,3)
           const float* __restrict__ b2)   // (3,)
{
    __shared__ __align__(16) float lat_s[128 * 68];  // [d_local][row], padded
    __shared__ float s_sum[64], s_sq[64];

    const int t = threadIdx.x;
    const int w = t >> 5, lane = t & 31;
    const int row0 = blockIdx.x * 64;
    const int rg = t >> 4;   // 0..7  -> rows rg*8 .. rg*8+7
    const int jg = t & 15;   // 0..15 -> cols jg*4 .. jg*4+3

    if (t < 64) { s_sum[t] = 0.f; s_sq[t] = 0.f; }

    // Preload per-thread invariant parameters
    float4 b1v  = __ldg(&((const float4*)b1)[jg]);
    float4 lngv = __ldg(&((const float4*)lng)[jg]);
    float4 lnbv = __ldg(&((const float4*)lnb)[jg]);
    float w2v[4][3];
    #pragma unroll
    for (int c = 0; c < 4; c++)
        #pragma unroll
        for (int kk = 0; kk < 3; kk++)
            w2v[c][kk] = __ldg(&w2[(jg * 4 + c) * 3 + kk]);

    float acc[8][4];
    #pragma unroll
    for (int i = 0; i < 8; i++)
        #pragma unroll
        for (int c = 0; c < 4; c++) acc[i][c] = 0.f;

    const float4* __restrict__ w1v = (const float4*)w1;  // [d][16]

    #pragma unroll 1
    for (int half = 0; half < 2; half++) {
        __syncthreads();   // s_sum init visible (h=0) / lat_s readers done (h=1)

        // fill: warp w owns rows w*16 .. w*16+15 (coalesced 512B per row)
        #pragma unroll 4
        for (int i = 0; i < 16; i++) {
            int r = w * 16 + i;
            float4 lv = __ldg((const float4*)(latents + (size_t)(row0 + r) * DD
                                              + half * 128) + lane);
            int d0 = lane * 4;
            lat_s[(d0 + 0) * 68 + r] = lv.x;
            lat_s[(d0 + 1) * 68 + r] = lv.y;
            lat_s[(d0 + 2) * 68 + r] = lv.z;
            lat_s[(d0 + 3) * 68 + r] = lv.w;
            float s = lv.x + lv.y + lv.z + lv.w;
            float q = lv.x*lv.x + lv.y*lv.y + lv.z*lv.z + lv.w*lv.w;
            s = warp_sum(s); q = warp_sum(q);
            if (lane == 0) { s_sum[r] += s; s_sq[r] += q; }
        }
        __syncthreads();

        // matvec over this half of D
        #pragma unroll 4
        for (int dl = 0; dl < 128; dl++) {
            float4 wv  = __ldg(&w1v[(half * 128 + dl) * 16 + jg]);
            float4 lv0 = *(const float4*)&lat_s[dl * 68 + rg * 8];
            float4 lv1 = *(const float4*)&lat_s[dl * 68 + rg * 8 + 4];
            #define K1ROW(i, comp) \
                acc[i][0] += (comp) * wv.x; acc[i][1] += (comp) * wv.y; \
                acc[i][2] += (comp) * wv.z; acc[i][3] += (comp) * wv.w;
            K1ROW(0, lv0.x) K1ROW(1, lv0.y) K1ROW(2, lv0.z) K1ROW(3, lv0.w)
            K1ROW(4, lv1.x) K1ROW(5, lv1.y) K1ROW(6, lv1.z) K1ROW(7, lv1.w)
            #undef K1ROW
        }
    }

    // std write (writes were completed before the last pre-matvec barrier)
    if (t < 64) {
        float s = s_sum[t], q = s_sq[t];
        float var = (q - s * s * (1.f / 256.f)) * (1.f / 255.f);
        g_std[row0 + t] = sqrtf(var);
    }

    float b20 = __ldg(&b2[0]), b21 = __ldg(&b2[1]), b22 = __ldg(&b2[2]);

    // gelu + LayerNorm + layer 2, all in registers; jg-group = half-warp
    #pragma unroll
    for (int rr = 0; rr < 8; rr++) {
        float h0 = gelu_exact(acc[rr][0] + b1v.x);
        float h1 = gelu_exact(acc[rr][1] + b1v.y);
        float h2 = gelu_exact(acc[rr][2] + b1v.z);
        float h3 = gelu_exact(acc[rr][3] + b1v.w);
        float sum = h0 + h1 + h2 + h3;
        float sq  = h0*h0 + h1*h1 + h2*h2 + h3*h3;
        #pragma unroll
        for (int o = 8; o > 0; o >>= 1) {
            sum += __shfl_xor_sync(0xffffffffu, sum, o);
            sq  += __shfl_xor_sync(0xffffffffu, sq,  o);
        }
        float mean = sum * (1.f / 64.f);
        float var  = sq * (1.f / 64.f) - mean * mean;
        float rstd = rsqrtf(var + 1e-5f);
        float n0 = (h0 - mean) * rstd * lngv.x + lnbv.x;
        float n1 = (h1 - mean) * rstd * lngv.y + lnbv.y;
        float n2 = (h2 - mean) * rstd * lngv.z + lnbv.z;
        float n3 = (h3 - mean) * rstd * lngv.w + lnbv.w;
        float m0 = n0*w2v[0][0] + n1*w2v[1][0] + n2*w2v[2][0] + n3*w2v[3][0];
        float m1 = n0*w2v[0][1] + n1*w2v[1][1] + n2*w2v[2][1] + n3*w2v[3][1];
        float m2 = n0*w2v[0][2] + n1*w2v[1][2] + n2*w2v[2][2] + n3*w2v[3][2];
        #pragma unroll
        for (int o = 8; o > 0; o >>= 1) {
            m0 += __shfl_xor_sync(0xffffffffu, m0, o);
            m1 += __shfl_xor_sync(0xffffffffu, m1, o);
            m2 += __shfl_xor_sync(0xffffffffu, m2, o);
        }
        if (jg == 0) {
            int row = row0 + rg * 8 + rr;
            g_mods[row * 3 + 0] = m0 + b20;
            g_mods[row * 3 + 1] = m1 + b21;
            g_mods[row * 3 + 2] = m2 + b22;
        }
    }
}

// ---------------------------------------------------------------------------
// K2: per-batch min/max of feature_std over L=4096.
// ---------------------------------------------------------------------------
__global__ void __launch_bounds__(256)
k2_minmax()
{
    __shared__ float smn[256], smx[256];
    const int b = blockIdx.x, t = threadIdx.x;
    float mn = 1e30f, mx = -1e30f;
    for (int i = t; i < LL; i += 256) {
        float v = g_std[b * LL + i];
        mn = fminf(mn, v); mx = fmaxf(mx, v);
    }
    smn[t] = mn; smx[t] = mx;
    __syncthreads();
    for (int s = 128; s > 0; s >>= 1) {
        if (t < s) { smn[t] = fminf(smn[t], smn[t + s]); smx[t] = fmaxf(smx[t], smx[t + s]); }
        __syncthreads();
    }
    if (t == 0) { g_mn[b] = smn[0]; g_mx[b] = smx[0]; }
}

// ---------------------------------------------------------------------------
// K3: streaming kernel, WARP PER ROW. 8 rows/block, 256 threads, no smem,
// no __syncthreads. Each warp streams 16 neighbor rows coalesced, reduces
// dot/normsq for 8 neighbors at a time via a butterfly transposition
// (31 shuffles instead of 16 serial warp_sums), then runs the epilogue
// itself — no idle warps holding block slots.
// ---------------------------------------------------------------------------
__global__ void __launch_bounds__(256)
k3_main(const float* __restrict__ latents,
        const float* __restrict__ attn,     // (B,H,L,17)
        const float* __restrict__ nfeat,    // (B,L,K,D)
        const float* __restrict__ npos,     // (B,L,K,2)
        const float* __restrict__ cpos,     // (B,L,2)
        const float* __restrict__ hw,       // (H,)
        const float* __restrict__ p_temp,
        const float* __restrict__ p_lba,
        const float* __restrict__ p_lbr,
        const float* __restrict__ p_imps,
        float* __restrict__ out)            // (B,L,2)
{
    const int w = threadIdx.x >> 5, lane = threadIdx.x & 31;
    const int bl = blockIdx.x * 8 + w;
    const int b = bl >> 12;
    const int l = bl & (LL - 1);

    // latent row, 8 floats per lane
    const float4* __restrict__ latv = (const float4*)(latents + (size_t)bl * DD);
    float4 l0 = __ldg(&latv[lane]);
    float4 l1 = __ldg(&latv[lane + 32]);
    float lsq = warp_sum(d4(l0, l0) + d4(l1, l1));
    float latn = fmaxf(sqrtf(lsq), 1e-8f);
    float inv_latn = 1.f / latn;

    const float4* __restrict__ nfb = (const float4*)(nfeat + ((size_t)bl * KN) * DD);

    float simc[2];
    #pragma unroll
    for (int c = 0; c < 2; c++) {
        float v[16];
        #pragma unroll
        for (int n = 0; n < 8; n++) {
            const float4* nf = nfb + (size_t)(c * 8 + n) * 64;
            float4 a0 = __ldg(&nf[lane]);
            float4 a1 = __ldg(&nf[lane + 32]);
            v[n]     = d4(a0, l0) + d4(a1, l1);   // dot partial
            v[8 + n] = d4(a0, a0) + d4(a1, a1);   // normsq partial
        }
        // butterfly transposition reduce: 16 values x 32 lanes -> lane holds
        // the full sum of logical value (lane & 15)
        #pragma unroll
        for (int j = 0; j < 8; j++) {
            float snd = (lane & 8) ? v[j] : v[j + 8];
            float kp  = (lane & 8) ? v[j + 8] : v[j];
            v[j] = kp + __shfl_xor_sync(0xffffffffu, snd, 8);
        }
        #pragma unroll
        for (int j = 0; j < 4; j++) {
            float snd = (lane & 4) ? v[j] : v[j + 4];
            float kp  = (lane & 4) ? v[j + 4] : v[j];
            v[j] = kp + __shfl_xor_sync(0xffffffffu, snd, 4);
        }
        #pragma unroll
        for (int j = 0; j < 2; j++) {
            float snd = (lane & 2) ? v[j] : v[j + 2];
            float kp  = (lane & 2) ? v[j + 2] : v[j];
            v[j] = kp + __shfl_xor_sync(0xffffffffu, snd, 2);
        }
        {
            float snd = (lane & 1) ? v[0] : v[1];
            float kp  = (lane & 1) ? v[1] : v[0];
            v[0] = kp + __shfl_xor_sync(0xffffffffu, snd, 1);
        }
        float tot = v[0] + __shfl_xor_sync(0xffffffffu, v[0], 16);
        // lanes with (lane&8)==0 hold dot(neighbor c*8+(lane&7));
        // lanes with (lane&8)!=0 hold normsq of the same neighbor.
        float nsq = __shfl_xor_sync(0xffffffffu, tot, 8);
        float nfn = fmaxf(sqrtf(nsq), 1e-8f);
        simc[c] = tot * inv_latn / nfn;   // valid where (lane&8)==0
    }
    float s0 = __shfl_sync(0xffffffffu, simc[0], lane & 7);
    float s1 = __shfl_sync(0xffffffffu, simc[1], lane & 7);
    float s  = (lane & 8) ? s1 : s0;   // lanes 0..15: sim of neighbor `lane`

    const bool act = lane < KN;
    float ssum = warp_sum(act ? s : 0.f);

    // head softmax (tiny, L1-resident)
    float hiv[HH];
    float hmax = -1e30f;
    #pragma unroll
    for (int h = 0; h < HH; h++) { hiv[h] = __ldg(&hw[h]); hmax = fmaxf(hmax, hiv[h]); }
    float hsum = 0.f;
    #pragma unroll
    for (int h = 0; h < HH; h++) { hiv[h] = expf(hiv[h] - hmax); hsum += hiv[h]; }
    float hinv = 1.f / hsum;

    float wa = 0.f;
    if (act) {
        const float* ap = attn + (((size_t)b * HH) * LL + l) * 17 + 1 + lane;
        #pragma unroll
        for (int h = 0; h < HH; h++)
            wa += hiv[h] * hinv * __ldg(&ap[(size_t)h * LL * 17]);
    }

    float2 np = make_float2(0.f, 0.f);
    if (act) np = ((const float2*)npos)[(size_t)bl * KN + lane];
    float2 cp = ((const float2*)cpos)[bl];
    float dx = np.x - cp.x, dy = np.y - cp.y;
    float dist = sqrtf(dx * dx + dy * dy);

    float temp = fabsf(__ldg(p_temp)) + 1e-8f;
    float rs = act ? (expf(s / temp) / (dist + 0.1f)) : 0.f;

    float inv_de = 1.f / (dist + 1e-8f);
    float wa_sum = warp_sum(wa);
    float rs_sum = warp_sum(rs);
    float wcx = warp_sum(wa * np.x);
    float wcy = warp_sum(wa * np.y);
    float rx  = warp_sum(act ? (rs * (-dx * inv_de)) : 0.f);
    float ry  = warp_sum(act ? (rs * (-dy * inv_de)) : 0.f);

    if (lane == 0) {
        float wan = 1.f / (wa_sum + 1e-8f);
        float rsn = 1.f / (rs_sum + 1e-8f);
        float ax = wcx * wan - cp.x;
        float ay = wcy * wan - cp.y;
        float rpx = rx * rsn;
        float rpy = ry * rsn;

        float uniq = 1.f - ssum * (1.f / (float)KN);
        float stdv = g_std[bl];
        float cmpx = (stdv - g_mn[b]) / (g_mx[b] - g_mn[b] + 1e-8f);
        float importance = 0.5f * cmpx + 0.5f * uniq;
        float imps = 1.f / (1.f + expf(-__ldg(p_imps)));
        float escale = 1.f - imps * importance;

        float m0 = g_mods[bl * 3 + 0];
        float m1 = g_mods[bl * 3 + 1];
        float m2 = g_mods[bl * 3 + 2];
        float w_at = expf(__ldg(p_lba)) * 2.f / (1.f + expf(-m0));
        float w_rp = expf(__ldg(p_lbr)) * 2.f / (1.f + expf(-m1));
        float fsc  = escale / (1.f + expf(-m2));
        float inv  = 1.f / (w_at + w_rp + 1e-8f);

        float cx = (w_at * ax + w_rp * rpx) * inv * fsc;
        float cy = (w_at * ay + w_rp * rpy) * inv * fsc;
        ((float2*)out)[bl] = make_float2(tanhf(cx * 0.2f) * 5.f,
                                         tanhf(cy * 0.2f) * 5.f);
    }
}

// ---------------------------------------------------------------------------
extern "C" void kernel_launch(void* const* d_in, const int* in_sizes, int n_in,
                              void* d_out, int out_size)
{
    (void)in_sizes; (void)n_in; (void)out_size;
    const float* latents = (const float*)d_in[0];
    const float* attn    = (const float*)d_in[1];
    const float* nfeat   = (const float*)d_in[2];
    const float* npos    = (const float*)d_in[3];
    const float* cpos    = (const float*)d_in[4];
    const float* hw      = (const float*)d_in[5];
    const float* p_temp  = (const float*)d_in[6];
    const float* p_lba   = (const float*)d_in[7];
    const float* p_lbr   = (const float*)d_in[8];
    const float* p_imps  = (const float*)d_in[9];
    const float* w1      = (const float*)d_in[10];
    const float* b1      = (const float*)d_in[11];
    const float* lng     = (const float*)d_in[12];
    const float* lnb     = (const float*)d_in[13];
    const float* w2      = (const float*)d_in[14];
    const float* b2      = (const float*)d_in[15];
    float* out = (float*)d_out;

    k1_std_mlp<<<NROWS / 64, 128>>>(latents, w1, b1, lng, lnb, w2, b2);
    k2_minmax<<<BB, 256>>>();
    k3_main<<<NROWS / 8, 256>>>(latents, attn, nfeat, npos, cpos, hw,
                                p_temp, p_lba, p_lbr, p_imps, out);
}

// round 8
// speedup vs baseline: 2.0728x; 1.3804x over previous
#include <cuda_runtime.h>
#include <cuda_bf16.h>
#include <math.h>

#define BB 8
#define HH 8
#define LL 4096
#define KN 16
#define DD 256
#define NROWS (BB*LL)          // 32768

// Scratch (no allocation allowed -> __device__ globals)
__device__ float g_std[NROWS];
__device__ float g_mods[NROWS*3];
__device__ float g_mn[BB];
__device__ float g_mx[BB];

__device__ __forceinline__ float warp_sum(float v) {
    #pragma unroll
    for (int o = 16; o > 0; o >>= 1) v += __shfl_xor_sync(0xffffffffu, v, o);
    return v;
}

__device__ __forceinline__ float gelu_exact(float x) {
    return 0.5f * x * (1.f + erff(x * 0.70710678118654752f));
}

__device__ __forceinline__ float d4(float4 a, float4 b) {
    return a.x*b.x + a.y*b.y + a.z*b.z + a.w*b.w;
}

// ---------------------------------------------------------------------------
// K0: per-row feature_std (ddof=1). Warp per row, pure streaming.
// ---------------------------------------------------------------------------
__global__ void __launch_bounds__(256)
k0_std(const float* __restrict__ latents)
{
    const int w = threadIdx.x >> 5, lane = threadIdx.x & 31;
    const int row = blockIdx.x * 8 + w;
    const float4* __restrict__ lp = (const float4*)(latents + (size_t)row * DD);
    float4 a = __ldg(&lp[lane]);
    float4 b = __ldg(&lp[lane + 32]);
    float s = a.x + a.y + a.z + a.w + b.x + b.y + b.z + b.w;
    float q = d4(a, a) + d4(b, b);
    s = warp_sum(s); q = warp_sum(q);
    if (lane == 0) {
        float var = (q - s * s * (1.f / 256.f)) * (1.f / 255.f);
        g_std[row] = sqrtf(var);
    }
}

// ---------------------------------------------------------------------------
// K1: MLP mods (latents @ w1 -> gelu -> LN -> @ w2). 32 rows/block, 1024
// blocks, 128 threads. Thread tile 4 rows x 4 cols. D processed in two
// 128-halves so the transposed latent tile is 18KB (high occupancy).
// Fill does a 4x4 register shuffle-transpose within lane quads + XOR-swizzled
// STS.128 -> conflict-free shared stores; matvec LDS.128 reads are
// warp-broadcast. LayerNorm + layer 2 entirely in registers (16-lane
// shuffles), no second smem buffer.
// ---------------------------------------------------------------------------
__global__ void __launch_bounds__(128)
k1_mlp(const float* __restrict__ latents,
       const float* __restrict__ w1,   // (256,64)
       const float* __restrict__ b1,   // (64,)
       const float* __restrict__ lng,  // (64,)
       const float* __restrict__ lnb,  // (64,)
       const float* __restrict__ w2,   // (64,3)
       const float* __restrict__ b2)   // (3,)
{
    // lat_s[dl][slot*4 + j]: stride 36 floats per dl; slot = rq ^ ((dl>>2)&7)
    __shared__ __align__(16) float lat_s[128 * 36];

    const int t = threadIdx.x;
    const int w = t >> 5, l = t & 31;
    const int row0 = blockIdx.x * 32;
    const int rg = t >> 4;   // 0..7  -> rows rg*4 .. rg*4+3
    const int jg = t & 15;   // 0..15 -> cols jg*4 .. jg*4+3

    const unsigned b8  = (l >> 3) & 1;
    const unsigned b16 = (l >> 4) & 1;
    const int i_quad = l >> 3;   // 0..3 (position within transpose quad)
    const int k_quad = l & 7;    // 0..7 (d-chunk id within 32-d stripe)

    float acc[4][4];
    #pragma unroll
    for (int i = 0; i < 4; i++)
        #pragma unroll
        for (int c = 0; c < 4; c++) acc[i][c] = 0.f;

    const float4* __restrict__ w1v = (const float4*)w1;  // [d][16]

    #pragma unroll 1
    for (int h = 0; h < 2; h++) {
        if (h) __syncthreads();   // lat_s readers of half 0 done

        // ---- fill (transposed, conflict-free) ----
        // warp w owns rows w*8 .. w*8+7. 8 instrs: (p = row sub-group, dq = d stripe)
        #pragma unroll
        for (int it = 0; it < 8; it++) {
            const int p  = it & 1;          // row sub-group (4 rows)
            const int dq = it >> 1;         // 32-d stripe 0..3
            const int r  = w * 8 + p * 4 + i_quad;
            const int dlb = dq * 32;
            float4 lv = __ldg((const float4*)(latents
                            + (size_t)(row0 + r) * DD + h * 128 + dlb) + k_quad);
            float a0 = lv.x, a1 = lv.y, a2 = lv.z, a3 = lv.w;
            // 4x4 transpose across lanes {k, k+8, k+16, k+24}
            {   // step 1: xor 8, pairs (0,1),(2,3)
                float s0 = b8 ? a0 : a1;
                float s1 = b8 ? a2 : a3;
                float r0 = __shfl_xor_sync(0xffffffffu, s0, 8);
                float r1 = __shfl_xor_sync(0xffffffffu, s1, 8);
                if (b8) { a0 = r0; a2 = r1; } else { a1 = r0; a3 = r1; }
            }
            {   // step 2: xor 16, pairs (0,2),(1,3)
                float s0 = b16 ? a0 : a2;
                float s1 = b16 ? a1 : a3;
                float r0 = __shfl_xor_sync(0xffffffffu, s0, 16);
                float r1 = __shfl_xor_sync(0xffffffffu, s1, 16);
                if (b16) { a0 = r0; a1 = r1; } else { a2 = r0; a3 = r1; }
            }
            // lane (i_quad, k_quad) now holds rows rq*4+0..3 at dl = dlb+4k+i
            const int rq = w * 2 + p;
            const int dl = dlb + 4 * k_quad + i_quad;
            const int slot = rq ^ k_quad;           // ((dl>>2)&7) == k_quad here
            float4 st = make_float4(a0, a1, a2, a3);
            *(float4*)&lat_s[dl * 36 + slot * 4] = st;
        }
        __syncthreads();

        // ---- matvec over this half of D ----
        #pragma unroll 2
        for (int dq4 = 0; dq4 < 32; dq4++) {        // groups of 4 dl
            const int slot = (rg ^ (dq4 & 7)) * 4;
            const float* __restrict__ base = &lat_s[(dq4 * 4) * 36 + slot];
            #pragma unroll
            for (int c = 0; c < 4; c++) {
                float4 wv = __ldg(&w1v[(h * 128 + dq4 * 4 + c) * 16 + jg]);
                float4 lv = *(const float4*)&base[c * 36];
                #define K1ROW(i, comp) \
                    acc[i][0] += (comp) * wv.x; acc[i][1] += (comp) * wv.y; \
                    acc[i][2] += (comp) * wv.z; acc[i][3] += (comp) * wv.w;
                K1ROW(0, lv.x) K1ROW(1, lv.y) K1ROW(2, lv.z) K1ROW(3, lv.w)
                #undef K1ROW
            }
        }
    }

    // ---- epilogue: gelu + LN + layer 2 in registers (16-lane groups) ----
    float4 b1v  = __ldg(&((const float4*)b1)[jg]);
    float4 lngv = __ldg(&((const float4*)lng)[jg]);
    float4 lnbv = __ldg(&((const float4*)lnb)[jg]);
    float w2v[4][3];
    #pragma unroll
    for (int c = 0; c < 4; c++)
        #pragma unroll
        for (int kk = 0; kk < 3; kk++)
            w2v[c][kk] = __ldg(&w2[(jg * 4 + c) * 3 + kk]);
    float b20 = __ldg(&b2[0]), b21 = __ldg(&b2[1]), b22 = __ldg(&b2[2]);

    #pragma unroll
    for (int rr = 0; rr < 4; rr++) {
        float h0 = gelu_exact(acc[rr][0] + b1v.x);
        float h1 = gelu_exact(acc[rr][1] + b1v.y);
        float h2 = gelu_exact(acc[rr][2] + b1v.z);
        float h3 = gelu_exact(acc[rr][3] + b1v.w);
        float sum = h0 + h1 + h2 + h3;
        float sq  = h0*h0 + h1*h1 + h2*h2 + h3*h3;
        #pragma unroll
        for (int o = 8; o > 0; o >>= 1) {
            sum += __shfl_xor_sync(0xffffffffu, sum, o);
            sq  += __shfl_xor_sync(0xffffffffu, sq,  o);
        }
        float mean = sum * (1.f / 64.f);
        float var  = sq * (1.f / 64.f) - mean * mean;
        float rstd = rsqrtf(var + 1e-5f);
        float n0 = (h0 - mean) * rstd * lngv.x + lnbv.x;
        float n1 = (h1 - mean) * rstd * lngv.y + lnbv.y;
        float n2 = (h2 - mean) * rstd * lngv.z + lnbv.z;
        float n3 = (h3 - mean) * rstd * lngv.w + lnbv.w;
        float m0 = n0*w2v[0][0] + n1*w2v[1][0] + n2*w2v[2][0] + n3*w2v[3][0];
        float m1 = n0*w2v[0][1] + n1*w2v[1][1] + n2*w2v[2][1] + n3*w2v[3][1];
        float m2 = n0*w2v[0][2] + n1*w2v[1][2] + n2*w2v[2][2] + n3*w2v[3][2];
        #pragma unroll
        for (int o = 8; o > 0; o >>= 1) {
            m0 += __shfl_xor_sync(0xffffffffu, m0, o);
            m1 += __shfl_xor_sync(0xffffffffu, m1, o);
            m2 += __shfl_xor_sync(0xffffffffu, m2, o);
        }
        if (jg == 0) {
            int row = row0 + rg * 4 + rr;
            g_mods[row * 3 + 0] = m0 + b20;
            g_mods[row * 3 + 1] = m1 + b21;
            g_mods[row * 3 + 2] = m2 + b22;
        }
    }
}

// ---------------------------------------------------------------------------
// K2: per-batch min/max of feature_std over L=4096.
// ---------------------------------------------------------------------------
__global__ void __launch_bounds__(256)
k2_minmax()
{
    __shared__ float smn[256], smx[256];
    const int b = blockIdx.x, t = threadIdx.x;
    float mn = 1e30f, mx = -1e30f;
    for (int i = t; i < LL; i += 256) {
        float v = g_std[b * LL + i];
        mn = fminf(mn, v); mx = fmaxf(mx, v);
    }
    smn[t] = mn; smx[t] = mx;
    __syncthreads();
    for (int s = 128; s > 0; s >>= 1) {
        if (t < s) { smn[t] = fminf(smn[t], smn[t + s]); smx[t] = fmaxf(smx[t], smx[t + s]); }
        __syncthreads();
    }
    if (t == 0) { g_mn[b] = smn[0]; g_mx[b] = smx[0]; }
}

// ---------------------------------------------------------------------------
// K3: streaming kernel, WARP PER ROW (unchanged from R6 — already at ~94% of
// the LTS cap). 8 rows/block, 256 threads, no smem, no __syncthreads.
// ---------------------------------------------------------------------------
__global__ void __launch_bounds__(256)
k3_main(const float* __restrict__ latents,
        const float* __restrict__ attn,     // (B,H,L,17)
        const float* __restrict__ nfeat,    // (B,L,K,D)
        const float* __restrict__ npos,     // (B,L,K,2)
        const float* __restrict__ cpos,     // (B,L,2)
        const float* __restrict__ hw,       // (H,)
        const float* __restrict__ p_temp,
        const float* __restrict__ p_lba,
        const float* __restrict__ p_lbr,
        const float* __restrict__ p_imps,
        float* __restrict__ out)            // (B,L,2)
{
    const int w = threadIdx.x >> 5, lane = threadIdx.x & 31;
    const int bl = blockIdx.x * 8 + w;
    const int b = bl >> 12;
    const int l = bl & (LL - 1);

    const float4* __restrict__ latv = (const float4*)(latents + (size_t)bl * DD);
    float4 l0 = __ldg(&latv[lane]);
    float4 l1 = __ldg(&latv[lane + 32]);
    float lsq = warp_sum(d4(l0, l0) + d4(l1, l1));
    float latn = fmaxf(sqrtf(lsq), 1e-8f);
    float inv_latn = 1.f / latn;

    const float4* __restrict__ nfb = (const float4*)(nfeat + ((size_t)bl * KN) * DD);

    float simc[2];
    #pragma unroll
    for (int c = 0; c < 2; c++) {
        float v[16];
        #pragma unroll
        for (int n = 0; n < 8; n++) {
            const float4* nf = nfb + (size_t)(c * 8 + n) * 64;
            float4 a0 = __ldg(&nf[lane]);
            float4 a1 = __ldg(&nf[lane + 32]);
            v[n]     = d4(a0, l0) + d4(a1, l1);   // dot partial
            v[8 + n] = d4(a0, a0) + d4(a1, a1);   // normsq partial
        }
        #pragma unroll
        for (int j = 0; j < 8; j++) {
            float snd = (lane & 8) ? v[j] : v[j + 8];
            float kp  = (lane & 8) ? v[j + 8] : v[j];
            v[j] = kp + __shfl_xor_sync(0xffffffffu, snd, 8);
        }
        #pragma unroll
        for (int j = 0; j < 4; j++) {
            float snd = (lane & 4) ? v[j] : v[j + 4];
            float kp  = (lane & 4) ? v[j + 4] : v[j];
            v[j] = kp + __shfl_xor_sync(0xffffffffu, snd, 4);
        }
        #pragma unroll
        for (int j = 0; j < 2; j++) {
            float snd = (lane & 2) ? v[j] : v[j + 2];
            float kp  = (lane & 2) ? v[j + 2] : v[j];
            v[j] = kp + __shfl_xor_sync(0xffffffffu, snd, 2);
        }
        {
            float snd = (lane & 1) ? v[0] : v[1];
            float kp  = (lane & 1) ? v[1] : v[0];
            v[0] = kp + __shfl_xor_sync(0xffffffffu, snd, 1);
        }
        float tot = v[0] + __shfl_xor_sync(0xffffffffu, v[0], 16);
        float nsq = __shfl_xor_sync(0xffffffffu, tot, 8);
        float nfn = fmaxf(sqrtf(nsq), 1e-8f);
        simc[c] = tot * inv_latn / nfn;
    }
    float s0 = __shfl_sync(0xffffffffu, simc[0], lane & 7);
    float s1 = __shfl_sync(0xffffffffu, simc[1], lane & 7);
    float s  = (lane & 8) ? s1 : s0;

    const bool act = lane < KN;
    float ssum = warp_sum(act ? s : 0.f);

    float hiv[HH];
    float hmax = -1e30f;
    #pragma unroll
    for (int h = 0; h < HH; h++) { hiv[h] = __ldg(&hw[h]); hmax = fmaxf(hmax, hiv[h]); }
    float hsum = 0.f;
    #pragma unroll
    for (int h = 0; h < HH; h++) { hiv[h] = expf(hiv[h] - hmax); hsum += hiv[h]; }
    float hinv = 1.f / hsum;

    float wa = 0.f;
    if (act) {
        const float* ap = attn + (((size_t)b * HH) * LL + l) * 17 + 1 + lane;
        #pragma unroll
        for (int h = 0; h < HH; h++)
            wa += hiv[h] * hinv * __ldg(&ap[(size_t)h * LL * 17]);
    }

    float2 np = make_float2(0.f, 0.f);
    if (act) np = ((const float2*)npos)[(size_t)bl * KN + lane];
    float2 cp = ((const float2*)cpos)[bl];
    float dx = np.x - cp.x, dy = np.y - cp.y;
    float dist = sqrtf(dx * dx + dy * dy);

    float temp = fabsf(__ldg(p_temp)) + 1e-8f;
    float rs = act ? (expf(s / temp) / (dist + 0.1f)) : 0.f;

    float inv_de = 1.f / (dist + 1e-8f);
    float wa_sum = warp_sum(wa);
    float rs_sum = warp_sum(rs);
    float wcx = warp_sum(wa * np.x);
    float wcy = warp_sum(wa * np.y);
    float rx  = warp_sum(act ? (rs * (-dx * inv_de)) : 0.f);
    float ry  = warp_sum(act ? (rs * (-dy * inv_de)) : 0.f);

    if (lane == 0) {
        float wan = 1.f / (wa_sum + 1e-8f);
        float rsn = 1.f / (rs_sum + 1e-8f);
        float ax = wcx * wan - cp.x;
        float ay = wcy * wan - cp.y;
        float rpx = rx * rsn;
        float rpy = ry * rsn;

        float uniq = 1.f - ssum * (1.f / (float)KN);
        float stdv = g_std[bl];
        float cmpx = (stdv - g_mn[b]) / (g_mx[b] - g_mn[b] + 1e-8f);
        float importance = 0.5f * cmpx + 0.5f * uniq;
        float imps = 1.f / (1.f + expf(-__ldg(p_imps)));
        float escale = 1.f - imps * importance;

        float m0 = g_mods[bl * 3 + 0];
        float m1 = g_mods[bl * 3 + 1];
        float m2 = g_mods[bl * 3 + 2];
        float w_at = expf(__ldg(p_lba)) * 2.f / (1.f + expf(-m0));
        float w_rp = expf(__ldg(p_lbr)) * 2.f / (1.f + expf(-m1));
        float fsc  = escale / (1.f + expf(-m2));
        float inv  = 1.f / (w_at + w_rp + 1e-8f);

        float cx = (w_at * ax + w_rp * rpx) * inv * fsc;
        float cy = (w_at * ay + w_rp * rpy) * inv * fsc;
        ((float2*)out)[bl] = make_float2(tanhf(cx * 0.2f) * 5.f,
                                         tanhf(cy * 0.2f) * 5.f);
    }
}

// ---------------------------------------------------------------------------
extern "C" void kernel_launch(void* const* d_in, const int* in_sizes, int n_in,
                              void* d_out, int out_size)
{
    (void)in_sizes; (void)n_in; (void)out_size;
    const float* latents = (const float*)d_in[0];
    const float* attn    = (const float*)d_in[1];
    const float* nfeat   = (const float*)d_in[2];
    const float* npos    = (const float*)d_in[3];
    const float* cpos    = (const float*)d_in[4];
    const float* hw      = (const float*)d_in[5];
    const float* p_temp  = (const float*)d_in[6];
    const float* p_lba   = (const float*)d_in[7];
    const float* p_lbr   = (const float*)d_in[8];
    const float* p_imps  = (const float*)d_in[9];
    const float* w1      = (const float*)d_in[10];
    const float* b1      = (const float*)d_in[11];
    const float* lng     = (const float*)d_in[12];
    const float* lnb     = (const float*)d_in[13];
    const float* w2      = (const float*)d_in[14];
    const float* b2      = (const float*)d_in[15];
    float* out = (float*)d_out;

    k0_std<<<NROWS / 8, 256>>>(latents);
    k1_mlp<<<NROWS / 32, 128>>>(latents, w1, b1, lng, lnb, w2, b2);
    k2_minmax<<<BB, 256>>>();
    k3_main<<<NROWS / 8, 256>>>(latents, attn, nfeat, npos, cpos, hw,
                                p_temp, p_lba, p_lbr, p_imps, out);
}

// round 10
// speedup vs baseline: 2.1283x; 1.0268x over previous
#include <cuda_runtime.h>
#include <cuda_bf16.h>
#include <math.h>

#define BB 8
#define HH 8
#define LL 4096
#define KN 16
#define DD 256
#define NROWS (BB*LL)          // 32768

// Scratch (no allocation allowed -> __device__ globals)
__device__ float g_std[NROWS];
__device__ float g_mods[NROWS*3];
__device__ float g_mn[BB];
__device__ float g_mx[BB];
__device__ float g_par[12];    // 0..7 head probs; 8 temp; 9 exp(lba)*2; 10 exp(lbr)*2; 11 sigmoid(imps)

__device__ __forceinline__ float warp_sum(float v) {
    #pragma unroll
    for (int o = 16; o > 0; o >>= 1) v += __shfl_xor_sync(0xffffffffu, v, o);
    return v;
}

__device__ __forceinline__ float gelu_exact(float x) {
    return 0.5f * x * (1.f + erff(x * 0.70710678118654752f));
}

__device__ __forceinline__ float d4(float4 a, float4 b) {
    return a.x*b.x + a.y*b.y + a.z*b.z + a.w*b.w;
}

// Packed f32x2 helpers (sm_103a)
__device__ __forceinline__ unsigned long long pack2(float v) {
    unsigned long long r;
    asm("mov.b64 %0, {%1, %1};" : "=l"(r) : "f"(v));
    return r;
}
__device__ __forceinline__ unsigned long long fma2(unsigned long long a,
                                                   unsigned long long b,
                                                   unsigned long long c) {
    unsigned long long d;
    asm("fma.rn.f32x2 %0, %1, %2, %3;" : "=l"(d) : "l"(a), "l"(b), "l"(c));
    return d;
}
__device__ __forceinline__ void unpack2(unsigned long long p, float& lo, float& hi) {
    asm("mov.b64 {%0, %1}, %2;" : "=f"(lo), "=f"(hi) : "l"(p));
}

// ---------------------------------------------------------------------------
// K01 fused: blocks [0,1024) run the MLP (32 rows each); blocks [1024,3072)
// compute per-row feature_std (16 rows each). The std blocks fill scheduler
// slack around the FFMA-heavy MLP blocks.
// ---------------------------------------------------------------------------
__global__ void __launch_bounds__(128)
k01_mlp_std(const float* __restrict__ latents,
            const float* __restrict__ w1,   // (256,64)
            const float* __restrict__ b1,   // (64,)
            const float* __restrict__ lng,  // (64,)
            const float* __restrict__ lnb,  // (64,)
            const float* __restrict__ w2,   // (64,3)
            const float* __restrict__ b2)   // (3,)
{
    const int t = threadIdx.x;
    const int w = t >> 5, l = t & 31;

    if (blockIdx.x >= 1024) {
        // ---------------- std path: 16 rows per block, warp does 4 ----------
        const int base = (blockIdx.x - 1024) * 16 + w * 4;
        #pragma unroll
        for (int i = 0; i < 4; i++) {
            const int row = base + i;
            const float4* __restrict__ lp = (const float4*)(latents + (size_t)row * DD);
            float4 a = __ldg(&lp[l]);
            float4 b = __ldg(&lp[l + 32]);
            float s = a.x + a.y + a.z + a.w + b.x + b.y + b.z + b.w;
            float q = d4(a, a) + d4(b, b);
            s = warp_sum(s); q = warp_sum(q);
            if (l == 0) {
                float var = (q - s * s * (1.f / 256.f)) * (1.f / 255.f);
                g_std[row] = sqrtf(var);
            }
        }
        return;
    }

    // ---------------- MLP path: 32 rows per block -------------------------
    // lat_s[dl][slot*4 + j]: stride 36 floats per dl; slot = rq ^ ((dl>>2)&7)
    __shared__ __align__(16) float lat_s[128 * 36];

    const int row0 = blockIdx.x * 32;
    const int rg = t >> 4;   // 0..7  -> rows rg*4 .. rg*4+3
    const int jg = t & 15;   // 0..15 -> cols jg*4 .. jg*4+3

    const unsigned b8  = (l >> 3) & 1;
    const unsigned b16 = (l >> 4) & 1;
    const int i_quad = l >> 3;   // 0..3
    const int k_quad = l & 7;    // 0..7

    // acc[row][pair]: pair 0 = cols (4jg, 4jg+1), pair 1 = cols (4jg+2, 4jg+3)
    unsigned long long acc[4][2];
    #pragma unroll
    for (int i = 0; i < 4; i++) { acc[i][0] = 0ull; acc[i][1] = 0ull; }

    // w1 row = 64 floats = 16 ulonglong2 elements -> stride 16 (BUGFIX: was 8)
    const ulonglong2* __restrict__ w1p = (const ulonglong2*)w1;

    #pragma unroll 1
    for (int h = 0; h < 2; h++) {
        if (h) __syncthreads();

        // ---- fill (transposed, conflict-free) ----
        #pragma unroll
        for (int it = 0; it < 8; it++) {
            const int p  = it & 1;
            const int dq = it >> 1;
            const int r  = w * 8 + p * 4 + i_quad;
            const int dlb = dq * 32;
            float4 lv = __ldg((const float4*)(latents
                            + (size_t)(row0 + r) * DD + h * 128 + dlb) + k_quad);
            float a0 = lv.x, a1 = lv.y, a2 = lv.z, a3 = lv.w;
            {   // transpose step 1: xor 8
                float s0 = b8 ? a0 : a1;
                float s1 = b8 ? a2 : a3;
                float r0 = __shfl_xor_sync(0xffffffffu, s0, 8);
                float r1 = __shfl_xor_sync(0xffffffffu, s1, 8);
                if (b8) { a0 = r0; a2 = r1; } else { a1 = r0; a3 = r1; }
            }
            {   // transpose step 2: xor 16
                float s0 = b16 ? a0 : a2;
                float s1 = b16 ? a1 : a3;
                float r0 = __shfl_xor_sync(0xffffffffu, s0, 16);
                float r1 = __shfl_xor_sync(0xffffffffu, s1, 16);
                if (b16) { a0 = r0; a1 = r1; } else { a2 = r0; a3 = r1; }
            }
            const int rq = w * 2 + p;
            const int dl = dlb + 4 * k_quad + i_quad;
            const int slot = rq ^ k_quad;
            *(float4*)&lat_s[dl * 36 + slot * 4] = make_float4(a0, a1, a2, a3);
        }
        __syncthreads();

        // ---- matvec over this half of D (packed f32x2) ----
        #pragma unroll 2
        for (int dq4 = 0; dq4 < 32; dq4++) {
            const int slot = (rg ^ (dq4 & 7)) * 4;
            const float* __restrict__ base = &lat_s[(dq4 * 4) * 36 + slot];
            #pragma unroll
            for (int c = 0; c < 4; c++) {
                ulonglong2 wv = __ldg(&w1p[((size_t)(h * 128 + dq4 * 4 + c)) * 16 + jg]);
                float4 lv = *(const float4*)&base[c * 36];
                unsigned long long p0 = pack2(lv.x);
                unsigned long long p1 = pack2(lv.y);
                unsigned long long p2 = pack2(lv.z);
                unsigned long long p3 = pack2(lv.w);
                acc[0][0] = fma2(p0, wv.x, acc[0][0]);
                acc[0][1] = fma2(p0, wv.y, acc[0][1]);
                acc[1][0] = fma2(p1, wv.x, acc[1][0]);
                acc[1][1] = fma2(p1, wv.y, acc[1][1]);
                acc[2][0] = fma2(p2, wv.x, acc[2][0]);
                acc[2][1] = fma2(p2, wv.y, acc[2][1]);
                acc[3][0] = fma2(p3, wv.x, acc[3][0]);
                acc[3][1] = fma2(p3, wv.y, acc[3][1]);
            }
        }
    }

    // ---- epilogue: gelu + LN + layer 2 in registers (16-lane groups) ----
    float4 b1v  = __ldg(&((const float4*)b1)[jg]);
    float4 lngv = __ldg(&((const float4*)lng)[jg]);
    float4 lnbv = __ldg(&((const float4*)lnb)[jg]);
    float w2v[4][3];
    #pragma unroll
    for (int c = 0; c < 4; c++)
        #pragma unroll
        for (int kk = 0; kk < 3; kk++)
            w2v[c][kk] = __ldg(&w2[(jg * 4 + c) * 3 + kk]);
    float b20 = __ldg(&b2[0]), b21 = __ldg(&b2[1]), b22 = __ldg(&b2[2]);

    #pragma unroll
    for (int rr = 0; rr < 4; rr++) {
        float a0, a1, a2, a3;
        unpack2(acc[rr][0], a0, a1);
        unpack2(acc[rr][1], a2, a3);
        float h0 = gelu_exact(a0 + b1v.x);
        float h1 = gelu_exact(a1 + b1v.y);
        float h2 = gelu_exact(a2 + b1v.z);
        float h3 = gelu_exact(a3 + b1v.w);
        float sum = h0 + h1 + h2 + h3;
        float sq  = h0*h0 + h1*h1 + h2*h2 + h3*h3;
        #pragma unroll
        for (int o = 8; o > 0; o >>= 1) {
            sum += __shfl_xor_sync(0xffffffffu, sum, o);
            sq  += __shfl_xor_sync(0xffffffffu, sq,  o);
        }
        float mean = sum * (1.f / 64.f);
        float var  = sq * (1.f / 64.f) - mean * mean;
        float rstd = rsqrtf(var + 1e-5f);
        float n0 = (h0 - mean) * rstd * lngv.x + lnbv.x;
        float n1 = (h1 - mean) * rstd * lngv.y + lnbv.y;
        float n2 = (h2 - mean) * rstd * lngv.z + lnbv.z;
        float n3 = (h3 - mean) * rstd * lngv.w + lnbv.w;
        float m0 = n0*w2v[0][0] + n1*w2v[1][0] + n2*w2v[2][0] + n3*w2v[3][0];
        float m1 = n0*w2v[0][1] + n1*w2v[1][1] + n2*w2v[2][1] + n3*w2v[3][1];
        float m2 = n0*w2v[0][2] + n1*w2v[1][2] + n2*w2v[2][2] + n3*w2v[3][2];
        #pragma unroll
        for (int o = 8; o > 0; o >>= 1) {
            m0 += __shfl_xor_sync(0xffffffffu, m0, o);
            m1 += __shfl_xor_sync(0xffffffffu, m1, o);
            m2 += __shfl_xor_sync(0xffffffffu, m2, o);
        }
        if (jg == 0) {
            int row = row0 + rg * 4 + rr;
            g_mods[row * 3 + 0] = m0 + b20;
            g_mods[row * 3 + 1] = m1 + b21;
            g_mods[row * 3 + 2] = m2 + b22;
        }
    }
}

// ---------------------------------------------------------------------------
// K2: per-batch min/max of feature_std + row-invariant scalar precompute.
// ---------------------------------------------------------------------------
__global__ void __launch_bounds__(256)
k2_minmax(const float* __restrict__ hw,
          const float* __restrict__ p_temp,
          const float* __restrict__ p_lba,
          const float* __restrict__ p_lbr,
          const float* __restrict__ p_imps)
{
    __shared__ float smn[256], smx[256];
    const int b = blockIdx.x, t = threadIdx.x;
    float mn = 1e30f, mx = -1e30f;
    for (int i = t; i < LL; i += 256) {
        float v = g_std[b * LL + i];
        mn = fminf(mn, v); mx = fmaxf(mx, v);
    }
    smn[t] = mn; smx[t] = mx;
    __syncthreads();
    for (int s = 128; s > 0; s >>= 1) {
        if (t < s) { smn[t] = fminf(smn[t], smn[t + s]); smx[t] = fmaxf(smx[t], smx[t + s]); }
        __syncthreads();
    }
    if (t == 0) {
        g_mn[b] = smn[0]; g_mx[b] = smx[0];
        if (b == 0) {
            float hv[HH], hmax = -1e30f;
            #pragma unroll
            for (int h = 0; h < HH; h++) { hv[h] = __ldg(&hw[h]); hmax = fmaxf(hmax, hv[h]); }
            float hs = 0.f;
            #pragma unroll
            for (int h = 0; h < HH; h++) { hv[h] = expf(hv[h] - hmax); hs += hv[h]; }
            #pragma unroll
            for (int h = 0; h < HH; h++) g_par[h] = hv[h] / hs;
            g_par[8]  = fabsf(__ldg(p_temp)) + 1e-8f;
            g_par[9]  = expf(__ldg(p_lba)) * 2.f;
            g_par[10] = expf(__ldg(p_lbr)) * 2.f;
            g_par[11] = 1.f / (1.f + expf(-__ldg(p_imps)));
        }
    }
}

// ---------------------------------------------------------------------------
// K3: streaming kernel, WARP PER ROW (structure unchanged — ~94% of LTS cap).
// Epilogue trimmed: row-invariant scalars come precomputed from g_par.
// ---------------------------------------------------------------------------
__global__ void __launch_bounds__(256)
k3_main(const float* __restrict__ latents,
        const float* __restrict__ attn,     // (B,H,L,17)
        const float* __restrict__ nfeat,    // (B,L,K,D)
        const float* __restrict__ npos,     // (B,L,K,2)
        const float* __restrict__ cpos,     // (B,L,2)
        float* __restrict__ out)            // (B,L,2)
{
    const int w = threadIdx.x >> 5, lane = threadIdx.x & 31;
    const int bl = blockIdx.x * 8 + w;
    const int b = bl >> 12;
    const int l = bl & (LL - 1);

    const float4* __restrict__ latv = (const float4*)(latents + (size_t)bl * DD);
    float4 l0 = __ldg(&latv[lane]);
    float4 l1 = __ldg(&latv[lane + 32]);
    float lsq = warp_sum(d4(l0, l0) + d4(l1, l1));
    float latn = fmaxf(sqrtf(lsq), 1e-8f);
    float inv_latn = 1.f / latn;

    const float4* __restrict__ nfb = (const float4*)(nfeat + ((size_t)bl * KN) * DD);

    float simc[2];
    #pragma unroll
    for (int c = 0; c < 2; c++) {
        float v[16];
        #pragma unroll
        for (int n = 0; n < 8; n++) {
            const float4* nf = nfb + (size_t)(c * 8 + n) * 64;
            float4 a0 = __ldg(&nf[lane]);
            float4 a1 = __ldg(&nf[lane + 32]);
            v[n]     = d4(a0, l0) + d4(a1, l1);   // dot partial
            v[8 + n] = d4(a0, a0) + d4(a1, a1);   // normsq partial
        }
        #pragma unroll
        for (int j = 0; j < 8; j++) {
            float snd = (lane & 8) ? v[j] : v[j + 8];
            float kp  = (lane & 8) ? v[j + 8] : v[j];
            v[j] = kp + __shfl_xor_sync(0xffffffffu, snd, 8);
        }
        #pragma unroll
        for (int j = 0; j < 4; j++) {
            float snd = (lane & 4) ? v[j] : v[j + 4];
            float kp  = (lane & 4) ? v[j + 4] : v[j];
            v[j] = kp + __shfl_xor_sync(0xffffffffu, snd, 4);
        }
        #pragma unroll
        for (int j = 0; j < 2; j++) {
            float snd = (lane & 2) ? v[j] : v[j + 2];
            float kp  = (lane & 2) ? v[j + 2] : v[j];
            v[j] = kp + __shfl_xor_sync(0xffffffffu, snd, 2);
        }
        {
            float snd = (lane & 1) ? v[0] : v[1];
            float kp  = (lane & 1) ? v[1] : v[0];
            v[0] = kp + __shfl_xor_sync(0xffffffffu, snd, 1);
        }
        float tot = v[0] + __shfl_xor_sync(0xffffffffu, v[0], 16);
        float nsq = __shfl_xor_sync(0xffffffffu, tot, 8);
        float nfn = fmaxf(sqrtf(nsq), 1e-8f);
        simc[c] = tot * inv_latn / nfn;
    }
    float s0 = __shfl_sync(0xffffffffu, simc[0], lane & 7);
    float s1 = __shfl_sync(0xffffffffu, simc[1], lane & 7);
    float s  = (lane & 8) ? s1 : s0;

    const bool act = lane < KN;
    float ssum = warp_sum(act ? s : 0.f);

    float wa = 0.f;
    if (act) {
        const float* ap = attn + (((size_t)b * HH) * LL + l) * 17 + 1 + lane;
        #pragma unroll
        for (int h = 0; h < HH; h++)
            wa += g_par[h] * __ldg(&ap[(size_t)h * LL * 17]);
    }

    float2 np = make_float2(0.f, 0.f);
    if (act) np = ((const float2*)npos)[(size_t)bl * KN + lane];
    float2 cp = ((const float2*)cpos)[bl];
    float dx = np.x - cp.x, dy = np.y - cp.y;
    float dist = sqrtf(dx * dx + dy * dy);

    float rs = act ? (__expf(s / g_par[8]) / (dist + 0.1f)) : 0.f;

    float inv_de = 1.f / (dist + 1e-8f);
    float wa_sum = warp_sum(wa);
    float rs_sum = warp_sum(rs);
    float wcx = warp_sum(wa * np.x);
    float wcy = warp_sum(wa * np.y);
    float rx  = warp_sum(act ? (rs * (-dx * inv_de)) : 0.f);
    float ry  = warp_sum(act ? (rs * (-dy * inv_de)) : 0.f);

    if (lane == 0) {
        float wan = 1.f / (wa_sum + 1e-8f);
        float rsn = 1.f / (rs_sum + 1e-8f);
        float ax = wcx * wan - cp.x;
        float ay = wcy * wan - cp.y;
        float rpx = rx * rsn;
        float rpy = ry * rsn;

        float uniq = 1.f - ssum * (1.f / (float)KN);
        float stdv = g_std[bl];
        float cmpx = (stdv - g_mn[b]) / (g_mx[b] - g_mn[b] + 1e-8f);
        float importance = 0.5f * cmpx + 0.5f * uniq;
        float escale = 1.f - g_par[11] * importance;

        float m0 = g_mods[bl * 3 + 0];
        float m1 = g_mods[bl * 3 + 1];
        float m2 = g_mods[bl * 3 + 2];
        float w_at = g_par[9]  / (1.f + __expf(-m0));
        float w_rp = g_par[10] / (1.f + __expf(-m1));
        float fsc  = escale / (1.f + __expf(-m2));
        float inv  = 1.f / (w_at + w_rp + 1e-8f);

        float cx = (w_at * ax + w_rp * rpx) * inv * fsc;
        float cy = (w_at * ay + w_rp * rpy) * inv * fsc;
        ((float2*)out)[bl] = make_float2(tanhf(cx * 0.2f) * 5.f,
                                         tanhf(cy * 0.2f) * 5.f);
    }
}

// ---------------------------------------------------------------------------
extern "C" void kernel_launch(void* const* d_in, const int* in_sizes, int n_in,
                              void* d_out, int out_size)
{
    (void)in_sizes; (void)n_in; (void)out_size;
    const float* latents = (const float*)d_in[0];
    const float* attn    = (const float*)d_in[1];
    const float* nfeat   = (const float*)d_in[2];
    const float* npos    = (const float*)d_in[3];
    const float* cpos    = (const float*)d_in[4];
    const float* hw      = (const float*)d_in[5];
    const float* p_temp  = (const float*)d_in[6];
    const float* p_lba   = (const float*)d_in[7];
    const float* p_lbr   = (const float*)d_in[8];
    const float* p_imps  = (const float*)d_in[9];
    const float* w1      = (const float*)d_in[10];
    const float* b1      = (const float*)d_in[11];
    const float* lng     = (const float*)d_in[12];
    const float* lnb     = (const float*)d_in[13];
    const float* w2      = (const float*)d_in[14];
    const float* b2      = (const float*)d_in[15];
    float* out = (float*)d_out;

    k01_mlp_std<<<1024 + 2048, 128>>>(latents, w1, b1, lng, lnb, w2, b2);
    k2_minmax<<<BB, 256>>>(hw, p_temp, p_lba, p_lbr, p_imps);
    k3_main<<<NROWS / 8, 256>>>(latents, attn, nfeat, npos, cpos, out);
}